// round 14
// baseline (speedup 1.0000x reference)
#include <cuda_runtime.h>
#include <cuda_bf16.h>
#include <cstdint>
#include <math.h>

// ---------------------------------------------------------------------------
// MLA forward. tf32 mma.sync GEMMs (64x64 warp tiles), ldmatrix fragments,
// pre-rounded inputs (single fused rounding pass), 5-stage cp.async,
// causal skipping, fused qa/kv GEMM.
// ---------------------------------------------------------------------------

static constexpr int BM = 128, BN = 128, BK = 16, PAD = 4, STAGES = 5;
static constexpr int BPAD_NT = 8;

// scratch
__device__ __align__(256) float g_qkv[2048L * 2112];
__device__ __align__(256) float g_qa[2048L * 1536];
__device__ __align__(256) float g_q [2048L * 6144];
__device__ __align__(256) float g_kf[2048L * 576];
__device__ __align__(256) float g_qf[2048L * 32 * 576];
__device__ __align__(256) float g_sc[2L * 32768 * 1024];
__device__ __align__(256) float g_oc[2048L * 32 * 512];
__device__ __align__(256) float g_ov[2048L * 4096];
// tf32-rounded inputs
__device__ __align__(256) float g_xr [2048L * 4096];
__device__ __align__(256) float g_w13[4096L * 2112];
__device__ __align__(256) float g_w2 [1536L * 6144];
__device__ __align__(256) float g_w4 [32L * 256 * 512];
__device__ __align__(256) float g_w5 [4096L * 4096];

__device__ __forceinline__ uint32_t f2tf(float f) {
    uint32_t u;
    asm("cvt.rna.tf32.f32 %0, %1;" : "=r"(u) : "f"(f));
    return u;
}
__device__ __forceinline__ float rtf(float f) { return __uint_as_float(f2tf(f)); }

__device__ __forceinline__ void cpa16(uint32_t smem, const float* g, bool pred) {
    int sz = pred ? 16 : 0;
    asm volatile("cp.async.cg.shared.global [%0], [%1], 16, %2;\n"
                 :: "r"(smem), "l"(g), "r"(sz));
}
__device__ __forceinline__ void cpa_commit() { asm volatile("cp.async.commit_group;\n"); }
template <int N> __device__ __forceinline__ void cpa_wait() {
    asm volatile("cp.async.wait_group %0;\n" :: "n"(N));
}
__device__ __forceinline__ uint32_t smem_u32(const void* p) {
    return (uint32_t)__cvta_generic_to_shared(p);
}
__device__ __forceinline__ void ldm4(uint32_t& r0, uint32_t& r1, uint32_t& r2,
                                     uint32_t& r3, uint32_t addr) {
    asm volatile("ldmatrix.sync.aligned.m8n8.x4.shared.b16 {%0,%1,%2,%3}, [%4];"
                 : "=r"(r0), "=r"(r1), "=r"(r2), "=r"(r3) : "r"(addr));
}
__device__ __forceinline__ void mma_tf32(float c[4], uint32_t a0, uint32_t a1,
                                         uint32_t a2, uint32_t a3,
                                         uint32_t b0, uint32_t b1) {
    asm volatile(
        "mma.sync.aligned.m16n8k8.row.col.f32.tf32.tf32.f32 "
        "{%0,%1,%2,%3},{%4,%5,%6,%7},{%8,%9},{%0,%1,%2,%3};\n"
        : "+f"(c[0]), "+f"(c[1]), "+f"(c[2]), "+f"(c[3])
        : "r"(a0), "r"(a1), "r"(a2), "r"(a3), "r"(b0), "r"(b1));
}

// ---------------------------------------------------------------------------
// One fused tf32 rounding pass over all inputs (float4 granularity).
// Segments: x->xr, wq_b->w2, wkv_b->w4, wo->w5, wq_a->w13[:, :1536],
// wkv_a->w13[:, 1536:2112].
// ---------------------------------------------------------------------------
__global__ void round_all(const float* __restrict__ x,  const float* __restrict__ wqb,
                          const float* __restrict__ wkvb, const float* __restrict__ wo,
                          const float* __restrict__ wqa, const float* __restrict__ wkva,
                          float* __restrict__ xr, float* __restrict__ w2,
                          float* __restrict__ w4, float* __restrict__ w5,
                          float* __restrict__ w13)
{
    const long N0 = 2097152;            // x        2048*4096/4
    const long N1 = N0 + 2359296;       // wq_b     1536*6144/4
    const long N2 = N1 + 1048576;       // wkv_b    32*256*512/4
    const long N3 = N2 + 4194304;       // wo       4096*4096/4
    const long N4 = N3 + 1572864;       // wq_a     4096*384
    const long N5 = N4 + 589824;        // wkv_a    4096*144
    long i = (long)blockIdx.x * blockDim.x + threadIdx.x;
    if (i >= N5) return;
    float4 v;
    float* outp;
    if (i < N0) {
        v = reinterpret_cast<const float4*>(x)[i];
        outp = xr + i * 4;
    } else if (i < N1) {
        long j = i - N0;
        v = reinterpret_cast<const float4*>(wqb)[j];
        outp = w2 + j * 4;
    } else if (i < N2) {
        long j = i - N1;
        v = reinterpret_cast<const float4*>(wkvb)[j];
        outp = w4 + j * 4;
    } else if (i < N3) {
        long j = i - N2;
        v = reinterpret_cast<const float4*>(wo)[j];
        outp = w5 + j * 4;
    } else if (i < N4) {
        long j = i - N3;
        long r = j / 384; int c4 = (int)(j - r * 384);
        v = reinterpret_cast<const float4*>(wqa)[j];
        outp = w13 + r * 2112 + c4 * 4;
    } else {
        long j = i - N4;
        long r = j / 144; int c4 = (int)(j - r * 144);
        v = reinterpret_cast<const float4*>(wkva)[j];
        outp = w13 + r * 2112 + 1536 + c4 * 4;
    }
    v.x = rtf(v.x); v.y = rtf(v.y); v.z = rtf(v.z); v.w = rtf(v.w);
    *reinterpret_cast<float4*>(outp) = v;
}

// ---------------------------------------------------------------------------
// C = A @ B (or A @ B^T if TB). 128 threads, 4 warps, 64x64 warp tiles.
// 5-stage cp.async pipeline (4 tiles in flight).
// ---------------------------------------------------------------------------
template <bool TB, bool CN, bool CK, bool RND>
__global__ __launch_bounds__(128, 2) void gemm_tc(
    const float* __restrict__ A, const float* __restrict__ B,
    float* __restrict__ C, int M, int N, int K,
    int lda, int ldb, int ldc, long sA, long sB, long sC)
{
    constexpr int BROWS = TB ? BN : BK;
    constexpr int BCOLS = TB ? (BK + PAD) : (BN + BPAD_NT);
    extern __shared__ __align__(16) float dyn[];
    float (*As)[BM][BK + PAD] = reinterpret_cast<float(*)[BM][BK + PAD]>(dyn);
    float (*Bs)[BROWS][BCOLS] =
        reinterpret_cast<float(*)[BROWS][BCOLS]>(dyn + STAGES * BM * (BK + PAD));

    const int n0 = blockIdx.x * BN;
    const int m0 = blockIdx.y * BM;
    const int W  = ((m0 >> 5) + 19) & ~15;
    if (CN && n0 >= W) return;
    const int Keff = CK ? (W < K ? W : K) : K;

    A += (long)blockIdx.z * sA;
    B += (long)blockIdx.z * sB;
    C += (long)blockIdx.z * sC;
    const int tid = threadIdx.x;
    const int warp = tid >> 5, lane = tid & 31;
    const int wm = warp & 1, wn = warp >> 1;          // 2 x 2 warp grid
    const int m0w = wm * 64, n0w = wn * 64;
    const int g = lane >> 2, t = lane & 3;

    const int ar   = lane & 15;
    const int asel = (lane >> 4) * 4;
    const int br   = (lane & 7) + ((lane >> 4) << 3);
    const int bsel = ((lane >> 3) & 1) * 4;

    float acc[4][8][4];
#pragma unroll
    for (int i = 0; i < 4; i++)
#pragma unroll
        for (int j = 0; j < 8; j++)
#pragma unroll
            for (int r = 0; r < 4; r++) acc[i][j][r] = 0.f;

    const int KT = Keff / BK;

    auto load_stage = [&](int st, int k0) {
#pragma unroll
        for (int c = tid; c < 512; c += 128) {
            int row = c >> 2, kc = (c & 3) * 4;
            uint32_t d = smem_u32(&As[st][row][kc]);
            cpa16(d, A + (long)(m0 + row) * lda + k0 + kc, true);
        }
        if (!TB) {
#pragma unroll
            for (int c = tid; c < 512; c += 128) {
                int row = c >> 5, col = (c & 31) * 4;
                bool v = (n0 + col) < N;
                uint32_t d = smem_u32(&Bs[st][row][col]);
                cpa16(d, B + (long)(k0 + row) * ldb + n0 + col, v);
            }
        } else {
#pragma unroll
            for (int c = tid; c < 512; c += 128) {
                int row = c >> 2, kc = (c & 3) * 4;
                bool v = (n0 + row) < N;
                uint32_t d = smem_u32(&Bs[st][row][kc]);
                cpa16(d, B + (long)(n0 + row) * ldb + k0 + kc, v);
            }
        }
        cpa_commit();
    };

    // prologue: 4 groups in flight
#pragma unroll
    for (int i = 0; i < 4; i++) {
        if (i < KT) load_stage(i, i * BK); else cpa_commit();
    }

    int st = 0, pst = 4;
    for (int kt = 0; kt < KT; ++kt) {
        cpa_wait<3>();
        __syncthreads();
        if (kt + 4 < KT) load_stage(pst, (kt + 4) * BK);
        else cpa_commit();
        if (++pst == STAGES) pst = 0;

#pragma unroll
        for (int ks = 0; ks < 2; ks++) {
            const int kk = ks * 8;
            uint32_t af[4][4], bf[8][2];
#pragma unroll
            for (int mt = 0; mt < 4; mt++) {
                ldm4(af[mt][0], af[mt][1], af[mt][2], af[mt][3],
                     smem_u32(&As[st][m0w + mt * 16 + ar][kk + asel]));
            }
            if (TB) {
#pragma unroll
                for (int ntp = 0; ntp < 4; ntp++) {
                    ldm4(bf[2 * ntp][0], bf[2 * ntp][1],
                         bf[2 * ntp + 1][0], bf[2 * ntp + 1][1],
                         smem_u32(&Bs[st][n0w + ntp * 16 + br][kk + bsel]));
                }
            } else {
#pragma unroll
                for (int nt = 0; nt < 8; nt++) {
                    const int nc = n0w + nt * 8 + g;
                    bf[nt][0] = __float_as_uint(Bs[st][kk + t][nc]);
                    bf[nt][1] = __float_as_uint(Bs[st][kk + t + 4][nc]);
                }
            }
#pragma unroll
            for (int mt = 0; mt < 4; mt++)
#pragma unroll
                for (int nt = 0; nt < 8; nt++)
                    mma_tf32(acc[mt][nt], af[mt][0], af[mt][1], af[mt][2], af[mt][3],
                             bf[nt][0], bf[nt][1]);
        }
        if (++st == STAGES) st = 0;
    }

    // epilogue
#pragma unroll
    for (int mt = 0; mt < 4; mt++) {
        const int mr = m0 + m0w + mt * 16 + g;
        float* Cp0 = C + (long)mr * ldc;
        float* Cp1 = C + (long)(mr + 8) * ldc;
#pragma unroll
        for (int nt = 0; nt < 8; nt++) {
            int gn = n0 + n0w + nt * 8 + t * 2;
            if (gn < N) {
                float4 v = make_float4(acc[mt][nt][0], acc[mt][nt][1],
                                       acc[mt][nt][2], acc[mt][nt][3]);
                if (RND) { v.x = rtf(v.x); v.y = rtf(v.y); v.z = rtf(v.z); v.w = rtf(v.w); }
                *reinterpret_cast<float2*>(Cp0 + gn) = make_float2(v.x, v.y);
                *reinterpret_cast<float2*>(Cp1 + gn) = make_float2(v.z, v.w);
            }
        }
    }
}

// ---------------------------------------------------------------------------
template <bool IS_MAX>
__device__ __forceinline__ float block_reduce(float v, float* sh)
{
    __syncthreads();
#pragma unroll
    for (int o = 16; o; o >>= 1) {
        float t = __shfl_xor_sync(0xffffffffu, v, o);
        v = IS_MAX ? fmaxf(v, t) : v + t;
    }
    const int lane = threadIdx.x & 31, w = threadIdx.x >> 5;
    if (lane == 0) sh[w] = v;
    __syncthreads();
    const int nw = blockDim.x >> 5;
    if (w == 0) {
        v = (lane < nw) ? sh[lane] : (IS_MAX ? -INFINITY : 0.f);
#pragma unroll
        for (int o = 16; o; o >>= 1) {
            float t = __shfl_xor_sync(0xffffffffu, v, o);
            v = IS_MAX ? fmaxf(v, t) : v + t;
        }
        if (lane == 0) sh[0] = v;
    }
    __syncthreads();
    return sh[0];
}

__global__ void rmsnorm_kernel(const float* __restrict__ in, const float* __restrict__ w,
                               float* __restrict__ out, int width, int ldin, int ldout)
{
    __shared__ float sh[32];
    const long row = blockIdx.x;
    const float* x = in + row * ldin;
    float* y = out + row * ldout;
    float ss = 0.f;
    for (int i = threadIdx.x; i < width; i += blockDim.x) {
        float v = x[i];
        ss += v * v;
    }
    float tot = block_reduce<false>(ss, sh);
    float rinv = rsqrtf(tot / (float)width + 1e-6f);
    for (int i = threadIdx.x; i < width; i += blockDim.x)
        y[i] = rtf(x[i] * rinv * w[i]);
}

// rope for k_pe: qkv[t, 2048:2112] -> kf[t, 512:576]
__global__ void rope_k(const float* __restrict__ qkv, const float* __restrict__ fc,
                       float* __restrict__ kf)
{
    int idx = blockIdx.x * blockDim.x + threadIdx.x;
    int t = idx >> 5, i = idx & 31;
    int pos = t & 1023;
    float c = fc[(pos * 32 + i) * 2 + 0];
    float s = fc[(pos * 32 + i) * 2 + 1];
    float xe = qkv[(long)t * 2112 + 2048 + 2 * i];
    float xo = qkv[(long)t * 2112 + 2049 + 2 * i];
    kf[(long)t * 576 + 512 + 2 * i] = rtf(xe * c - xo * s);
    kf[(long)t * 576 + 513 + 2 * i] = rtf(xe * s + xo * c);
}

__global__ void rope_q(const float* __restrict__ q, const float* __restrict__ fc,
                       float* __restrict__ qf)
{
    long idx = (long)blockIdx.x * blockDim.x + threadIdx.x;
    int i = idx & 31;
    int h = (idx >> 5) & 31;
    long r = idx >> 10;
    int pos = (int)(r & 1023);
    const float* src = q + r * 6144 + h * 192 + 128 + 2 * i;
    float xe = src[0], xo = src[1];
    float c = fc[(pos * 32 + i) * 2 + 0];
    float s = fc[(pos * 32 + i) * 2 + 1];
    float* dst = qf + (r * 32 + h) * 576 + 512 + 2 * i;
    dst[0] = rtf(xe * c - xo * s);
    dst[1] = rtf(xe * s + xo * c);
}

// softmax: one block per (b,s); 32 rows (heads), 8 threads/row.
__global__ __launch_bounds__(256) void softmax_kernel(float* __restrict__ sc,
                                                      const float* __restrict__ mask)
{
    const int bs = blockIdx.x;
    const int b = bs >> 10, s = bs & 1023;
    const int W = ((s & ~3) + 19) & ~15;
    const int r = threadIdx.x >> 3;
    const int t = threadIdx.x & 7;
    float* p = sc + ((long)b * 32768 + s * 32 + r) * 1024;
    const float* mk = mask + (long)s * 1024;
    const float scale = 0.07216878364870322f;

    float mx = -INFINITY;
    for (int j = t; j < W; j += 8)
        mx = fmaxf(mx, p[j] * scale + mk[j]);
#pragma unroll
    for (int o = 4; o; o >>= 1)
        mx = fmaxf(mx, __shfl_xor_sync(0xffffffffu, mx, o));

    float sum = 0.f;
    for (int j = t; j < W; j += 8) {
        float e = expf(p[j] * scale + mk[j] - mx);
        p[j] = e;
        sum += e;
    }
#pragma unroll
    for (int o = 4; o; o >>= 1)
        sum += __shfl_xor_sync(0xffffffffu, sum, o);
    float inv = 1.f / sum;
    for (int j = t; j < W; j += 8)
        p[j] = rtf(p[j] * inv);
}

// ---------------------------------------------------------------------------
extern "C" void kernel_launch(void* const* d_in, const int* in_sizes, int n_in,
                              void* d_out, int out_size)
{
    const float* x        = (const float*)d_in[0];
    const float* fc       = (const float*)d_in[1];
    const float* mask     = (const float*)d_in[2];
    const float* wq_a     = (const float*)d_in[3];
    const float* q_norm_w = (const float*)d_in[4];
    const float* wq_b     = (const float*)d_in[5];
    const float* wkv_a    = (const float*)d_in[6];
    const float* kv_norm_w= (const float*)d_in[7];
    const float* wkv_b    = (const float*)d_in[8];
    const float* wo       = (const float*)d_in[9];
    float* out = (float*)d_out;

    float *qkv, *qa, *q, *kf, *qf, *sc, *oc, *ov;
    float *xr, *w13, *w2, *w4, *w5;
    cudaGetSymbolAddress((void**)&qkv, g_qkv);
    cudaGetSymbolAddress((void**)&qa, g_qa);
    cudaGetSymbolAddress((void**)&q,  g_q);
    cudaGetSymbolAddress((void**)&kf, g_kf);
    cudaGetSymbolAddress((void**)&qf, g_qf);
    cudaGetSymbolAddress((void**)&sc, g_sc);
    cudaGetSymbolAddress((void**)&oc, g_oc);
    cudaGetSymbolAddress((void**)&ov, g_ov);
    cudaGetSymbolAddress((void**)&xr, g_xr);
    cudaGetSymbolAddress((void**)&w13, g_w13);
    cudaGetSymbolAddress((void**)&w2, g_w2);
    cudaGetSymbolAddress((void**)&w4, g_w4);
    cudaGetSymbolAddress((void**)&w5, g_w5);

    const int SM_NT = STAGES * (BM * (BK + PAD) + BK * (BN + BPAD_NT)) * 4;
    const int SM_TB = STAGES * (BM * (BK + PAD) + BN * (BK + PAD)) * 4;
    cudaFuncSetAttribute(gemm_tc<false, false, false, false>,
                         cudaFuncAttributeMaxDynamicSharedMemorySize, SM_NT);
    cudaFuncSetAttribute(gemm_tc<false, false, false, true>,
                         cudaFuncAttributeMaxDynamicSharedMemorySize, SM_NT);
    cudaFuncSetAttribute(gemm_tc<true, true, false, false>,
                         cudaFuncAttributeMaxDynamicSharedMemorySize, SM_TB);
    cudaFuncSetAttribute(gemm_tc<false, false, true, true>,
                         cudaFuncAttributeMaxDynamicSharedMemorySize, SM_NT);
    cudaFuncSetAttribute(gemm_tc<true, false, false, true>,
                         cudaFuncAttributeMaxDynamicSharedMemorySize, SM_TB);

    const dim3 blk(128);

    // 1: fused rounding of all inputs (single launch)
    {
        const long total = 2097152L + 2359296 + 1048576 + 4194304 + 1572864 + 589824;
        round_all<<<(int)((total + 255) / 256), 256>>>(
            x, wq_b, wkv_b, wo, wq_a, wkv_a, xr, w2, w4, w5, w13);
    }
    // 2: qkv = x @ [wq_a | wkv_a]
    gemm_tc<false, false, false, false><<<dim3(17, 16, 1), blk, SM_NT>>>(
        xr, w13, qkv, 2048, 2112, 4096, 4096, 2112, 2112, 0, 0, 0);
    // 3: qa = rmsnorm(qkv[:, :1536])
    rmsnorm_kernel<<<2048, 256>>>(qkv, q_norm_w, qa, 1536, 2112, 1536);
    // 4: kf rmsnorm part
    rmsnorm_kernel<<<2048, 256>>>(qkv + 1536, kv_norm_w, kf, 512, 2112, 576);
    // 5: kf rope part
    rope_k<<<256, 256>>>(qkv, fc, kf);
    // 6: q = qa @ wq_b   (<- ncu -s 5 -c 1 captures this launch)
    gemm_tc<false, false, false, true><<<dim3(48, 16, 1), blk, SM_NT>>>(
        qa, w2, q, 2048, 6144, 1536, 1536, 6144, 6144, 0, 0, 0);
    // 7: q_pe rope
    rope_q<<<2048, 1024>>>(q, fc, qf);
    // 8: q absorb (z = h)
    gemm_tc<false, false, false, true><<<dim3(4, 16, 32), blk, SM_NT>>>(
        q, w4, qf, 2048, 512, 128, 6144, 512, 32 * 576,
        192, 256L * 512, 576);
    // 9: scores (z = b, TB, causal skip)
    gemm_tc<true, true, false, false><<<dim3(8, 256, 2), blk, SM_TB>>>(
        qf, kf, sc, 32768, 1024, 576, 576, 576, 1024,
        32768L * 576, 1024L * 576, 32768L * 1024);
    // 10: softmax
    softmax_kernel<<<2048, 256>>>(sc, mask);
    // 11: PV (z = b, causal K clamp)
    gemm_tc<false, false, true, true><<<dim3(4, 256, 2), blk, SM_NT>>>(
        sc, kf, oc, 32768, 512, 1024, 1024, 576, 512,
        32768L * 1024, 1024L * 576, 32768L * 512);
    // 12: v proj (z = h, TB)
    gemm_tc<true, false, false, true><<<dim3(1, 16, 32), blk, SM_TB>>>(
        oc, w4 + 128 * 512, ov, 2048, 128, 512, 32 * 512, 512, 4096,
        512, 256L * 512, 128);
    // 13: out = ov @ wo
    gemm_tc<false, false, false, false><<<dim3(32, 16, 1), blk, SM_NT>>>(
        ov, w5, out, 2048, 4096, 4096, 4096, 4096, 4096, 0, 0, 0);
}

// round 15
// speedup vs baseline: 1.0520x; 1.0520x over previous
#include <cuda_runtime.h>
#include <cuda_bf16.h>
#include <cstdint>
#include <math.h>

// ---------------------------------------------------------------------------
// MLA forward. tf32 mma.sync GEMMs (64x64 warp tiles), ldmatrix fragments,
// pre-rounded inputs (single fused rounding pass), 4-stage cp.async,
// causal skipping, fused qa/kv GEMM.  (R13 GEMM config + R14 round_all.)
// ---------------------------------------------------------------------------

static constexpr int BM = 128, BN = 128, BK = 16, PAD = 4, STAGES = 4;
static constexpr int BPAD_NT = 8;

// scratch
__device__ __align__(256) float g_qkv[2048L * 2112];
__device__ __align__(256) float g_qa[2048L * 1536];
__device__ __align__(256) float g_q [2048L * 6144];
__device__ __align__(256) float g_kf[2048L * 576];
__device__ __align__(256) float g_qf[2048L * 32 * 576];
__device__ __align__(256) float g_sc[2L * 32768 * 1024];
__device__ __align__(256) float g_oc[2048L * 32 * 512];
__device__ __align__(256) float g_ov[2048L * 4096];
// tf32-rounded inputs
__device__ __align__(256) float g_xr [2048L * 4096];
__device__ __align__(256) float g_w13[4096L * 2112];
__device__ __align__(256) float g_w2 [1536L * 6144];
__device__ __align__(256) float g_w4 [32L * 256 * 512];
__device__ __align__(256) float g_w5 [4096L * 4096];

__device__ __forceinline__ uint32_t f2tf(float f) {
    uint32_t u;
    asm("cvt.rna.tf32.f32 %0, %1;" : "=r"(u) : "f"(f));
    return u;
}
__device__ __forceinline__ float rtf(float f) { return __uint_as_float(f2tf(f)); }

__device__ __forceinline__ void cpa16(uint32_t smem, const float* g, bool pred) {
    int sz = pred ? 16 : 0;
    asm volatile("cp.async.cg.shared.global [%0], [%1], 16, %2;\n"
                 :: "r"(smem), "l"(g), "r"(sz));
}
__device__ __forceinline__ void cpa_commit() { asm volatile("cp.async.commit_group;\n"); }
template <int N> __device__ __forceinline__ void cpa_wait() {
    asm volatile("cp.async.wait_group %0;\n" :: "n"(N));
}
__device__ __forceinline__ uint32_t smem_u32(const void* p) {
    return (uint32_t)__cvta_generic_to_shared(p);
}
__device__ __forceinline__ void ldm4(uint32_t& r0, uint32_t& r1, uint32_t& r2,
                                     uint32_t& r3, uint32_t addr) {
    asm volatile("ldmatrix.sync.aligned.m8n8.x4.shared.b16 {%0,%1,%2,%3}, [%4];"
                 : "=r"(r0), "=r"(r1), "=r"(r2), "=r"(r3) : "r"(addr));
}
__device__ __forceinline__ void mma_tf32(float c[4], uint32_t a0, uint32_t a1,
                                         uint32_t a2, uint32_t a3,
                                         uint32_t b0, uint32_t b1) {
    asm volatile(
        "mma.sync.aligned.m16n8k8.row.col.f32.tf32.tf32.f32 "
        "{%0,%1,%2,%3},{%4,%5,%6,%7},{%8,%9},{%0,%1,%2,%3};\n"
        : "+f"(c[0]), "+f"(c[1]), "+f"(c[2]), "+f"(c[3])
        : "r"(a0), "r"(a1), "r"(a2), "r"(a3), "r"(b0), "r"(b1));
}

// ---------------------------------------------------------------------------
// One fused tf32 rounding pass over all inputs (float4 granularity).
// ---------------------------------------------------------------------------
__global__ void round_all(const float* __restrict__ x,  const float* __restrict__ wqb,
                          const float* __restrict__ wkvb, const float* __restrict__ wo,
                          const float* __restrict__ wqa, const float* __restrict__ wkva,
                          float* __restrict__ xr, float* __restrict__ w2,
                          float* __restrict__ w4, float* __restrict__ w5,
                          float* __restrict__ w13)
{
    const long N0 = 2097152;            // x        2048*4096/4
    const long N1 = N0 + 2359296;       // wq_b     1536*6144/4
    const long N2 = N1 + 1048576;       // wkv_b    32*256*512/4
    const long N3 = N2 + 4194304;       // wo       4096*4096/4
    const long N4 = N3 + 1572864;       // wq_a     4096*384
    const long N5 = N4 + 589824;        // wkv_a    4096*144
    long i = (long)blockIdx.x * blockDim.x + threadIdx.x;
    if (i >= N5) return;
    float4 v;
    float* outp;
    if (i < N0) {
        v = reinterpret_cast<const float4*>(x)[i];
        outp = xr + i * 4;
    } else if (i < N1) {
        long j = i - N0;
        v = reinterpret_cast<const float4*>(wqb)[j];
        outp = w2 + j * 4;
    } else if (i < N2) {
        long j = i - N1;
        v = reinterpret_cast<const float4*>(wkvb)[j];
        outp = w4 + j * 4;
    } else if (i < N3) {
        long j = i - N2;
        v = reinterpret_cast<const float4*>(wo)[j];
        outp = w5 + j * 4;
    } else if (i < N4) {
        long j = i - N3;
        long r = j / 384; int c4 = (int)(j - r * 384);
        v = reinterpret_cast<const float4*>(wqa)[j];
        outp = w13 + r * 2112 + c4 * 4;
    } else {
        long j = i - N4;
        long r = j / 144; int c4 = (int)(j - r * 144);
        v = reinterpret_cast<const float4*>(wkva)[j];
        outp = w13 + r * 2112 + 1536 + c4 * 4;
    }
    v.x = rtf(v.x); v.y = rtf(v.y); v.z = rtf(v.z); v.w = rtf(v.w);
    *reinterpret_cast<float4*>(outp) = v;
}

// ---------------------------------------------------------------------------
// C = A @ B (or A @ B^T if TB). 128 threads, 4 warps, 64x64 warp tiles.
// 4-stage cp.async (3 tiles in flight).
// ---------------------------------------------------------------------------
template <bool TB, bool CN, bool CK, bool RND>
__global__ __launch_bounds__(128, 2) void gemm_tc(
    const float* __restrict__ A, const float* __restrict__ B,
    float* __restrict__ C, int M, int N, int K,
    int lda, int ldb, int ldc, long sA, long sB, long sC)
{
    constexpr int BROWS = TB ? BN : BK;
    constexpr int BCOLS = TB ? (BK + PAD) : (BN + BPAD_NT);
    extern __shared__ __align__(16) float dyn[];
    float (*As)[BM][BK + PAD] = reinterpret_cast<float(*)[BM][BK + PAD]>(dyn);
    float (*Bs)[BROWS][BCOLS] =
        reinterpret_cast<float(*)[BROWS][BCOLS]>(dyn + STAGES * BM * (BK + PAD));

    const int n0 = blockIdx.x * BN;
    const int m0 = blockIdx.y * BM;
    const int W  = ((m0 >> 5) + 19) & ~15;
    if (CN && n0 >= W) return;
    const int Keff = CK ? (W < K ? W : K) : K;

    A += (long)blockIdx.z * sA;
    B += (long)blockIdx.z * sB;
    C += (long)blockIdx.z * sC;
    const int tid = threadIdx.x;
    const int warp = tid >> 5, lane = tid & 31;
    const int wm = warp & 1, wn = warp >> 1;          // 2 x 2 warp grid
    const int m0w = wm * 64, n0w = wn * 64;
    const int g = lane >> 2, t = lane & 3;

    const int ar   = lane & 15;
    const int asel = (lane >> 4) * 4;
    const int br   = (lane & 7) + ((lane >> 4) << 3);
    const int bsel = ((lane >> 3) & 1) * 4;

    float acc[4][8][4];
#pragma unroll
    for (int i = 0; i < 4; i++)
#pragma unroll
        for (int j = 0; j < 8; j++)
#pragma unroll
            for (int r = 0; r < 4; r++) acc[i][j][r] = 0.f;

    const int KT = Keff / BK;

    auto load_stage = [&](int st, int k0) {
#pragma unroll
        for (int c = tid; c < 512; c += 128) {
            int row = c >> 2, kc = (c & 3) * 4;
            uint32_t d = smem_u32(&As[st][row][kc]);
            cpa16(d, A + (long)(m0 + row) * lda + k0 + kc, true);
        }
        if (!TB) {
#pragma unroll
            for (int c = tid; c < 512; c += 128) {
                int row = c >> 5, col = (c & 31) * 4;
                bool v = (n0 + col) < N;
                uint32_t d = smem_u32(&Bs[st][row][col]);
                cpa16(d, B + (long)(k0 + row) * ldb + n0 + col, v);
            }
        } else {
#pragma unroll
            for (int c = tid; c < 512; c += 128) {
                int row = c >> 2, kc = (c & 3) * 4;
                bool v = (n0 + row) < N;
                uint32_t d = smem_u32(&Bs[st][row][kc]);
                cpa16(d, B + (long)(n0 + row) * ldb + k0 + kc, v);
            }
        }
        cpa_commit();
    };

    load_stage(0, 0);
    if (KT > 1) load_stage(1, BK); else cpa_commit();
    if (KT > 2) load_stage(2, 2 * BK); else cpa_commit();

    for (int kt = 0; kt < KT; ++kt) {
        cpa_wait<2>();
        __syncthreads();
        if (kt + 3 < KT) load_stage((kt + 3) & 3, (kt + 3) * BK);
        else cpa_commit();
        const int st = kt & 3;

#pragma unroll
        for (int ks = 0; ks < 2; ks++) {
            const int kk = ks * 8;
            uint32_t af[4][4], bf[8][2];
#pragma unroll
            for (int mt = 0; mt < 4; mt++) {
                ldm4(af[mt][0], af[mt][1], af[mt][2], af[mt][3],
                     smem_u32(&As[st][m0w + mt * 16 + ar][kk + asel]));
            }
            if (TB) {
#pragma unroll
                for (int ntp = 0; ntp < 4; ntp++) {
                    ldm4(bf[2 * ntp][0], bf[2 * ntp][1],
                         bf[2 * ntp + 1][0], bf[2 * ntp + 1][1],
                         smem_u32(&Bs[st][n0w + ntp * 16 + br][kk + bsel]));
                }
            } else {
#pragma unroll
                for (int nt = 0; nt < 8; nt++) {
                    const int nc = n0w + nt * 8 + g;
                    bf[nt][0] = __float_as_uint(Bs[st][kk + t][nc]);
                    bf[nt][1] = __float_as_uint(Bs[st][kk + t + 4][nc]);
                }
            }
#pragma unroll
            for (int mt = 0; mt < 4; mt++)
#pragma unroll
                for (int nt = 0; nt < 8; nt++)
                    mma_tf32(acc[mt][nt], af[mt][0], af[mt][1], af[mt][2], af[mt][3],
                             bf[nt][0], bf[nt][1]);
        }
    }

    // epilogue
#pragma unroll
    for (int mt = 0; mt < 4; mt++) {
        const int mr = m0 + m0w + mt * 16 + g;
        float* Cp0 = C + (long)mr * ldc;
        float* Cp1 = C + (long)(mr + 8) * ldc;
#pragma unroll
        for (int nt = 0; nt < 8; nt++) {
            int gn = n0 + n0w + nt * 8 + t * 2;
            if (gn < N) {
                float4 v = make_float4(acc[mt][nt][0], acc[mt][nt][1],
                                       acc[mt][nt][2], acc[mt][nt][3]);
                if (RND) { v.x = rtf(v.x); v.y = rtf(v.y); v.z = rtf(v.z); v.w = rtf(v.w); }
                *reinterpret_cast<float2*>(Cp0 + gn) = make_float2(v.x, v.y);
                *reinterpret_cast<float2*>(Cp1 + gn) = make_float2(v.z, v.w);
            }
        }
    }
}

// ---------------------------------------------------------------------------
template <bool IS_MAX>
__device__ __forceinline__ float block_reduce(float v, float* sh)
{
    __syncthreads();
#pragma unroll
    for (int o = 16; o; o >>= 1) {
        float t = __shfl_xor_sync(0xffffffffu, v, o);
        v = IS_MAX ? fmaxf(v, t) : v + t;
    }
    const int lane = threadIdx.x & 31, w = threadIdx.x >> 5;
    if (lane == 0) sh[w] = v;
    __syncthreads();
    const int nw = blockDim.x >> 5;
    if (w == 0) {
        v = (lane < nw) ? sh[lane] : (IS_MAX ? -INFINITY : 0.f);
#pragma unroll
        for (int o = 16; o; o >>= 1) {
            float t = __shfl_xor_sync(0xffffffffu, v, o);
            v = IS_MAX ? fmaxf(v, t) : v + t;
        }
        if (lane == 0) sh[0] = v;
    }
    __syncthreads();
    return sh[0];
}

__global__ void rmsnorm_kernel(const float* __restrict__ in, const float* __restrict__ w,
                               float* __restrict__ out, int width, int ldin, int ldout)
{
    __shared__ float sh[32];
    const long row = blockIdx.x;
    const float* x = in + row * ldin;
    float* y = out + row * ldout;
    float ss = 0.f;
    for (int i = threadIdx.x; i < width; i += blockDim.x) {
        float v = x[i];
        ss += v * v;
    }
    float tot = block_reduce<false>(ss, sh);
    float rinv = rsqrtf(tot / (float)width + 1e-6f);
    for (int i = threadIdx.x; i < width; i += blockDim.x)
        y[i] = rtf(x[i] * rinv * w[i]);
}

// rope for k_pe: qkv[t, 2048:2112] -> kf[t, 512:576]
__global__ void rope_k(const float* __restrict__ qkv, const float* __restrict__ fc,
                       float* __restrict__ kf)
{
    int idx = blockIdx.x * blockDim.x + threadIdx.x;
    int t = idx >> 5, i = idx & 31;
    int pos = t & 1023;
    float c = fc[(pos * 32 + i) * 2 + 0];
    float s = fc[(pos * 32 + i) * 2 + 1];
    float xe = qkv[(long)t * 2112 + 2048 + 2 * i];
    float xo = qkv[(long)t * 2112 + 2049 + 2 * i];
    kf[(long)t * 576 + 512 + 2 * i] = rtf(xe * c - xo * s);
    kf[(long)t * 576 + 513 + 2 * i] = rtf(xe * s + xo * c);
}

__global__ void rope_q(const float* __restrict__ q, const float* __restrict__ fc,
                       float* __restrict__ qf)
{
    long idx = (long)blockIdx.x * blockDim.x + threadIdx.x;
    int i = idx & 31;
    int h = (idx >> 5) & 31;
    long r = idx >> 10;
    int pos = (int)(r & 1023);
    const float* src = q + r * 6144 + h * 192 + 128 + 2 * i;
    float xe = src[0], xo = src[1];
    float c = fc[(pos * 32 + i) * 2 + 0];
    float s = fc[(pos * 32 + i) * 2 + 1];
    float* dst = qf + (r * 32 + h) * 576 + 512 + 2 * i;
    dst[0] = rtf(xe * c - xo * s);
    dst[1] = rtf(xe * s + xo * c);
}

// softmax: one block per (b,s); 32 rows (heads), 8 threads/row.
__global__ __launch_bounds__(256) void softmax_kernel(float* __restrict__ sc,
                                                      const float* __restrict__ mask)
{
    const int bs = blockIdx.x;
    const int b = bs >> 10, s = bs & 1023;
    const int W = ((s & ~3) + 19) & ~15;
    const int r = threadIdx.x >> 3;
    const int t = threadIdx.x & 7;
    float* p = sc + ((long)b * 32768 + s * 32 + r) * 1024;
    const float* mk = mask + (long)s * 1024;
    const float scale = 0.07216878364870322f;

    float mx = -INFINITY;
    for (int j = t; j < W; j += 8)
        mx = fmaxf(mx, p[j] * scale + mk[j]);
#pragma unroll
    for (int o = 4; o; o >>= 1)
        mx = fmaxf(mx, __shfl_xor_sync(0xffffffffu, mx, o));

    float sum = 0.f;
    for (int j = t; j < W; j += 8) {
        float e = expf(p[j] * scale + mk[j] - mx);
        p[j] = e;
        sum += e;
    }
#pragma unroll
    for (int o = 4; o; o >>= 1)
        sum += __shfl_xor_sync(0xffffffffu, sum, o);
    float inv = 1.f / sum;
    for (int j = t; j < W; j += 8)
        p[j] = rtf(p[j] * inv);
}

// ---------------------------------------------------------------------------
extern "C" void kernel_launch(void* const* d_in, const int* in_sizes, int n_in,
                              void* d_out, int out_size)
{
    const float* x        = (const float*)d_in[0];
    const float* fc       = (const float*)d_in[1];
    const float* mask     = (const float*)d_in[2];
    const float* wq_a     = (const float*)d_in[3];
    const float* q_norm_w = (const float*)d_in[4];
    const float* wq_b     = (const float*)d_in[5];
    const float* wkv_a    = (const float*)d_in[6];
    const float* kv_norm_w= (const float*)d_in[7];
    const float* wkv_b    = (const float*)d_in[8];
    const float* wo       = (const float*)d_in[9];
    float* out = (float*)d_out;

    float *qkv, *qa, *q, *kf, *qf, *sc, *oc, *ov;
    float *xr, *w13, *w2, *w4, *w5;
    cudaGetSymbolAddress((void**)&qkv, g_qkv);
    cudaGetSymbolAddress((void**)&qa, g_qa);
    cudaGetSymbolAddress((void**)&q,  g_q);
    cudaGetSymbolAddress((void**)&kf, g_kf);
    cudaGetSymbolAddress((void**)&qf, g_qf);
    cudaGetSymbolAddress((void**)&sc, g_sc);
    cudaGetSymbolAddress((void**)&oc, g_oc);
    cudaGetSymbolAddress((void**)&ov, g_ov);
    cudaGetSymbolAddress((void**)&xr, g_xr);
    cudaGetSymbolAddress((void**)&w13, g_w13);
    cudaGetSymbolAddress((void**)&w2, g_w2);
    cudaGetSymbolAddress((void**)&w4, g_w4);
    cudaGetSymbolAddress((void**)&w5, g_w5);

    const int SM_NT = STAGES * (BM * (BK + PAD) + BK * (BN + BPAD_NT)) * 4;
    const int SM_TB = STAGES * (BM * (BK + PAD) + BN * (BK + PAD)) * 4;
    cudaFuncSetAttribute(gemm_tc<false, false, false, false>,
                         cudaFuncAttributeMaxDynamicSharedMemorySize, SM_NT);
    cudaFuncSetAttribute(gemm_tc<false, false, false, true>,
                         cudaFuncAttributeMaxDynamicSharedMemorySize, SM_NT);
    cudaFuncSetAttribute(gemm_tc<true, true, false, false>,
                         cudaFuncAttributeMaxDynamicSharedMemorySize, SM_TB);
    cudaFuncSetAttribute(gemm_tc<false, false, true, true>,
                         cudaFuncAttributeMaxDynamicSharedMemorySize, SM_NT);
    cudaFuncSetAttribute(gemm_tc<true, false, false, true>,
                         cudaFuncAttributeMaxDynamicSharedMemorySize, SM_TB);

    const dim3 blk(128);

    // fused rounding of all inputs (single launch)
    {
        const long total = 2097152L + 2359296 + 1048576 + 4194304 + 1572864 + 589824;
        round_all<<<(int)((total + 255) / 256), 256>>>(
            x, wq_b, wkv_b, wo, wq_a, wkv_a, xr, w2, w4, w5, w13);
    }
    // qkv = x @ [wq_a | wkv_a]
    gemm_tc<false, false, false, false><<<dim3(17, 16, 1), blk, SM_NT>>>(
        xr, w13, qkv, 2048, 2112, 4096, 4096, 2112, 2112, 0, 0, 0);
    // qa = rmsnorm(qkv[:, :1536])
    rmsnorm_kernel<<<2048, 256>>>(qkv, q_norm_w, qa, 1536, 2112, 1536);
    // q = qa @ wq_b
    gemm_tc<false, false, false, true><<<dim3(48, 16, 1), blk, SM_NT>>>(
        qa, w2, q, 2048, 6144, 1536, 1536, 6144, 6144, 0, 0, 0);
    // kf
    rmsnorm_kernel<<<2048, 256>>>(qkv + 1536, kv_norm_w, kf, 512, 2112, 576);
    rope_k<<<256, 256>>>(qkv, fc, kf);
    // q_pe rope
    rope_q<<<2048, 1024>>>(q, fc, qf);
    // q absorb (z = h)
    gemm_tc<false, false, false, true><<<dim3(4, 16, 32), blk, SM_NT>>>(
        q, w4, qf, 2048, 512, 128, 6144, 512, 32 * 576,
        192, 256L * 512, 576);
    // scores (z = b, TB, causal skip)
    gemm_tc<true, true, false, false><<<dim3(8, 256, 2), blk, SM_TB>>>(
        qf, kf, sc, 32768, 1024, 576, 576, 576, 1024,
        32768L * 576, 1024L * 576, 32768L * 1024);
    // softmax
    softmax_kernel<<<2048, 256>>>(sc, mask);
    // PV (z = b, causal K clamp)
    gemm_tc<false, false, true, true><<<dim3(4, 256, 2), blk, SM_NT>>>(
        sc, kf, oc, 32768, 512, 1024, 1024, 576, 512,
        32768L * 1024, 1024L * 576, 32768L * 512);
    // v proj (z = h, TB)
    gemm_tc<true, false, false, true><<<dim3(1, 16, 32), blk, SM_TB>>>(
        oc, w4 + 128 * 512, ov, 2048, 128, 512, 32 * 512, 512, 4096,
        512, 256L * 512, 128);
    // out = ov @ wo
    gemm_tc<false, false, false, false><<<dim3(32, 16, 1), blk, SM_NT>>>(
        ov, w5, out, 2048, 4096, 4096, 4096, 4096, 4096, 0, 0, 0);
}